// round 1
// baseline (speedup 1.0000x reference)
#include <cuda_runtime.h>

// Problem constants (fixed shapes from reference)
#define BB 4
#define NN 19
#define HH 512
#define WW 512
#define HWc (HH * WW)          // 262144
#define CC 57
#define PAIRS (BB * NN)        // 76
#define TILES 32
#define THREADS 256
#define V_PER_TILE (HWc / 4 / TILES)        // 2048 float4 per tile
#define V_PER_THREAD (V_PER_TILE / THREADS) // 8 float4 per thread per plane

__device__ float g_bce[PAIRS];
__device__ float g_l1x[PAIRS];
__device__ float g_l1y[PAIRS];
__device__ float g_cnt[PAIRS];

__global__ void hm_zero_kernel() {
    int i = threadIdx.x;
    if (i < PAIRS) {
        g_bce[i] = 0.0f;
        g_l1x[i] = 0.0f;
        g_l1y[i] = 0.0f;
        g_cnt[i] = 0.0f;
    }
}

__global__ __launch_bounds__(THREADS) void hm_main_kernel(
    const float* __restrict__ fm, const float* __restrict__ lms)
{
    const int pair = blockIdx.x / TILES;
    const int tile = blockIdx.x % TILES;
    const int b = pair / NN;
    const int n = pair % NN;

    // landmark -> integer center (matches (lm * [H,W]).astype(int32) truncation)
    const float lx = lms[pair * 2 + 0];
    const float ly = lms[pair * 2 + 1];
    const int x = (int)(lx * (float)HH);
    const int y = (int)(ly * (float)WW);

    const size_t base = ((size_t)(b * CC + n)) * (size_t)HWc;
    const float4* __restrict__ pL = (const float4*)(fm + base);
    const float4* __restrict__ pX = (const float4*)(fm + base + (size_t)NN * HWc);
    const float4* __restrict__ pY = (const float4*)(fm + base + (size_t)(2 * NN) * HWc);

    float bce = 0.0f, l1x = 0.0f, l1y = 0.0f;
    int cnt = 0;

    const int vbase = tile * V_PER_TILE + threadIdx.x;

    #pragma unroll
    for (int k = 0; k < V_PER_THREAD; k++) {
        const int v = vbase + k * THREADS;
        const float4 L  = __ldg(pL + v);
        const float4 PX = __ldg(pX + v);
        const float4 PY = __ldg(pY + v);

        const int h = v >> 7;           // v / 128 (128 float4 per row)
        const int w = (v & 127) << 2;   // starting column of this float4

        const int di = h - x;           // row delta (constant across the 4 lanes)
        const int di2 = di * di;
        const float offx = -(float)di * (1.0f / 40.0f);

        float Lv[4]  = {L.x, L.y, L.z, L.w};
        float PXv[4] = {PX.x, PX.y, PX.z, PX.w};
        float PYv[4] = {PY.x, PY.y, PY.z, PY.w};

        #pragma unroll
        for (int j = 0; j < 4; j++) {
            const int dj = (w + j) - y;
            const bool heat = (di2 + dj * dj) <= 1600;   // == (sqrt(d2) <= 40)
            const float l = Lv[j];
            // bce elem = max(l,0) - l*heat + log1p(exp(-|l|))
            const float sp = log1pf(__expf(-fabsf(l)));
            bce += fmaxf(l, 0.0f) + sp - (heat ? l : 0.0f);
            if (heat) {
                const float offy = -(float)dj * (1.0f / 40.0f);
                l1x += fabsf(PXv[j] - offx);
                l1y += fabsf(PYv[j] - offy);
                cnt++;
            }
        }
    }

    // block reduction: warp shfl, then cross-warp via smem, then atomicAdd
    float c = (float)cnt;
    #pragma unroll
    for (int o = 16; o > 0; o >>= 1) {
        bce += __shfl_down_sync(0xFFFFFFFFu, bce, o);
        l1x += __shfl_down_sync(0xFFFFFFFFu, l1x, o);
        l1y += __shfl_down_sync(0xFFFFFFFFu, l1y, o);
        c   += __shfl_down_sync(0xFFFFFFFFu, c, o);
    }

    __shared__ float s0[8], s1[8], s2[8], s3[8];
    const int warp = threadIdx.x >> 5;
    const int lane = threadIdx.x & 31;
    if (lane == 0) { s0[warp] = bce; s1[warp] = l1x; s2[warp] = l1y; s3[warp] = c; }
    __syncthreads();

    if (warp == 0) {
        float v0 = (lane < 8) ? s0[lane] : 0.0f;
        float v1 = (lane < 8) ? s1[lane] : 0.0f;
        float v2 = (lane < 8) ? s2[lane] : 0.0f;
        float v3 = (lane < 8) ? s3[lane] : 0.0f;
        #pragma unroll
        for (int o = 4; o > 0; o >>= 1) {
            v0 += __shfl_down_sync(0xFFFFFFFFu, v0, o);
            v1 += __shfl_down_sync(0xFFFFFFFFu, v1, o);
            v2 += __shfl_down_sync(0xFFFFFFFFu, v2, o);
            v3 += __shfl_down_sync(0xFFFFFFFFu, v3, o);
        }
        if (lane == 0) {
            atomicAdd(&g_bce[pair], v0);
            atomicAdd(&g_l1x[pair], v1);
            atomicAdd(&g_l1y[pair], v2);
            atomicAdd(&g_cnt[pair], v3);
        }
    }
}

__global__ void hm_final_kernel(float* __restrict__ out) {
    const int i = threadIdx.x;   // 128 threads
    float t = 0.0f;
    if (i < PAIRS) {
        t = 2.0f * g_bce[i] * (1.0f / (float)HWc)
          + (g_l1x[i] + g_l1y[i]) / g_cnt[i];
    }
    #pragma unroll
    for (int o = 16; o > 0; o >>= 1)
        t += __shfl_down_sync(0xFFFFFFFFu, t, o);

    __shared__ float s[4];
    const int warp = i >> 5, lane = i & 31;
    if (lane == 0) s[warp] = t;
    __syncthreads();
    if (i == 0) {
        float sum = s[0] + s[1] + s[2] + s[3];
        out[0] = sum / (float)PAIRS;
    }
}

extern "C" void kernel_launch(void* const* d_in, const int* in_sizes, int n_in,
                              void* d_out, int out_size)
{
    const float* fm  = (const float*)d_in[0];   // feature_maps (4,57,512,512) f32
    const float* lms = (const float*)d_in[1];   // landmarks (4,19,2) f32
    float* out = (float*)d_out;

    hm_zero_kernel<<<1, 128>>>();
    hm_main_kernel<<<PAIRS * TILES, THREADS>>>(fm, lms);
    hm_final_kernel<<<1, 128>>>(out);
}

// round 2
// speedup vs baseline: 1.2923x; 1.2923x over previous
#include <cuda_runtime.h>

// Problem constants (fixed shapes from reference)
#define BB 4
#define NN 19
#define HH 512
#define WW 512
#define HWc (HH * WW)          // 262144
#define CC 57
#define PAIRS (BB * NN)        // 76
#define TILES 32
#define NBLOCKS (PAIRS * TILES)             // 2432
#define THREADS 256
#define V_PER_TILE (HWc / 4 / TILES)        // 2048 float4 per tile
#define V_PER_THREAD (V_PER_TILE / THREADS) // 8 float4 per thread per plane

// Per-CTA partials: every slot written each launch -> no zero kernel needed.
__device__ float g_pbce[NBLOCKS];
__device__ float g_pl1x[NBLOCKS];
__device__ float g_pl1y[NBLOCKS];
__device__ float g_pcnt[NBLOCKS];

__global__ __launch_bounds__(THREADS) void hm_main_kernel(
    const float* __restrict__ fm, const float* __restrict__ lms)
{
    const int pair = blockIdx.x / TILES;
    const int tile = blockIdx.x % TILES;
    const int b = pair / NN;
    const int n = pair % NN;

    // landmark -> integer center (matches (lm * [H,W]).astype(int32) truncation)
    const float lx = lms[pair * 2 + 0];
    const float ly = lms[pair * 2 + 1];
    const int x = (int)(lx * (float)HH);
    const int y = (int)(ly * (float)WW);

    const size_t base = ((size_t)(b * CC + n)) * (size_t)HWc;
    const float4* __restrict__ pL = (const float4*)(fm + base);
    const float4* __restrict__ pX = (const float4*)(fm + base + (size_t)NN * HWc);
    const float4* __restrict__ pY = (const float4*)(fm + base + (size_t)(2 * NN) * HWc);

    float bce = 0.0f, l1x = 0.0f, l1y = 0.0f;
    int cnt = 0;

    const int vbase = tile * V_PER_TILE + threadIdx.x;

    #pragma unroll
    for (int k = 0; k < V_PER_THREAD; k++) {
        const int v = vbase + k * THREADS;
        const float4 L  = __ldcs(pL + v);   // evict-streaming: no reuse, 239MB stream
        const float4 PX = __ldcs(pX + v);
        const float4 PY = __ldcs(pY + v);

        const int h = v >> 7;           // v / 128 (128 float4 per row)
        const int w = (v & 127) << 2;   // starting column of this float4

        const int di = h - x;           // row delta (constant across the 4 lanes)
        const int di2 = di * di;
        const float offx = -(float)di * (1.0f / 40.0f);

        float Lv[4]  = {L.x, L.y, L.z, L.w};
        float PXv[4] = {PX.x, PX.y, PX.z, PX.w};
        float PYv[4] = {PY.x, PY.y, PY.z, PY.w};

        #pragma unroll
        for (int j = 0; j < 4; j++) {
            const int dj = (w + j) - y;
            const bool heat = (di2 + dj * dj) <= 1600;   // == (sqrt(d2) <= 40)
            const float l = Lv[j];
            // softplus(-|l|) via fast MUFU log/exp (rel_err budget is 1e-3; this is ~1e-6)
            const float sp = __logf(1.0f + __expf(-fabsf(l)));
            bce += fmaxf(l, 0.0f) + sp - (heat ? l : 0.0f);
            if (heat) {
                const float offy = -(float)dj * (1.0f / 40.0f);
                l1x += fabsf(PXv[j] - offx);
                l1y += fabsf(PYv[j] - offy);
                cnt++;
            }
        }
    }

    // block reduction: warp shfl, then cross-warp via smem, then per-CTA store
    float c = (float)cnt;
    #pragma unroll
    for (int o = 16; o > 0; o >>= 1) {
        bce += __shfl_down_sync(0xFFFFFFFFu, bce, o);
        l1x += __shfl_down_sync(0xFFFFFFFFu, l1x, o);
        l1y += __shfl_down_sync(0xFFFFFFFFu, l1y, o);
        c   += __shfl_down_sync(0xFFFFFFFFu, c, o);
    }

    __shared__ float s0[8], s1[8], s2[8], s3[8];
    const int warp = threadIdx.x >> 5;
    const int lane = threadIdx.x & 31;
    if (lane == 0) { s0[warp] = bce; s1[warp] = l1x; s2[warp] = l1y; s3[warp] = c; }
    __syncthreads();

    if (warp == 0) {
        float v0 = (lane < 8) ? s0[lane] : 0.0f;
        float v1 = (lane < 8) ? s1[lane] : 0.0f;
        float v2 = (lane < 8) ? s2[lane] : 0.0f;
        float v3 = (lane < 8) ? s3[lane] : 0.0f;
        #pragma unroll
        for (int o = 4; o > 0; o >>= 1) {
            v0 += __shfl_down_sync(0xFFFFFFFFu, v0, o);
            v1 += __shfl_down_sync(0xFFFFFFFFu, v1, o);
            v2 += __shfl_down_sync(0xFFFFFFFFu, v2, o);
            v3 += __shfl_down_sync(0xFFFFFFFFu, v3, o);
        }
        if (lane == 0) {
            g_pbce[blockIdx.x] = v0;
            g_pl1x[blockIdx.x] = v1;
            g_pl1y[blockIdx.x] = v2;
            g_pcnt[blockIdx.x] = v3;
        }
    }
}

// Single block, 1024 threads. Warp w handles pairs w, w+32, w+64; lane = tile.
__global__ __launch_bounds__(1024) void hm_final_kernel(float* __restrict__ out) {
    const int warp = threadIdx.x >> 5;
    const int lane = threadIdx.x & 31;

    float acc = 0.0f;
    for (int pair = warp; pair < PAIRS; pair += 32) {
        const int idx = pair * TILES + lane;   // TILES == 32 == warp width
        float bce = g_pbce[idx];
        float l1x = g_pl1x[idx];
        float l1y = g_pl1y[idx];
        float cnt = g_pcnt[idx];
        #pragma unroll
        for (int o = 16; o > 0; o >>= 1) {
            bce += __shfl_down_sync(0xFFFFFFFFu, bce, o);
            l1x += __shfl_down_sync(0xFFFFFFFFu, l1x, o);
            l1y += __shfl_down_sync(0xFFFFFFFFu, l1y, o);
            cnt += __shfl_down_sync(0xFFFFFFFFu, cnt, o);
        }
        if (lane == 0)
            acc += 2.0f * bce * (1.0f / (float)HWc) + (l1x + l1y) / cnt;
    }

    __shared__ float s[32];
    if (lane == 0) s[warp] = acc;
    __syncthreads();
    if (warp == 0) {
        float v = s[lane];
        #pragma unroll
        for (int o = 16; o > 0; o >>= 1)
            v += __shfl_down_sync(0xFFFFFFFFu, v, o);
        if (lane == 0) out[0] = v / (float)PAIRS;
    }
}

extern "C" void kernel_launch(void* const* d_in, const int* in_sizes, int n_in,
                              void* d_out, int out_size)
{
    const float* fm  = (const float*)d_in[0];   // feature_maps (4,57,512,512) f32
    const float* lms = (const float*)d_in[1];   // landmarks (4,19,2) f32
    float* out = (float*)d_out;

    hm_main_kernel<<<NBLOCKS, THREADS>>>(fm, lms);
    hm_final_kernel<<<1, 1024>>>(out);
}